// round 15
// baseline (speedup 1.0000x reference)
#include <cuda_runtime.h>
#include <cuda_bf16.h>
#include <cuda_fp16.h>
#include <mma.h>
#include <cstdint>

using namespace nvcuda;

#define DIN 128
#define DOUT 128
#define NEG_SLOPE 0.2f
#define MAX_N 50048
#define MAX_EN 860000   // E + N with slack

// ---------------- scratch (no allocations allowed) ----------------
__device__ float    g_xw[(size_t)MAX_N * DOUT];   // x @ W (fp32 staging)
__device__ __half   g_xw_h[(size_t)MAX_N * DOUT]; // x @ W (fp16, for gather)
__device__ float    g_asrc[MAX_N];
__device__ float    g_adst[MAX_N];
__device__ int      g_deg[MAX_N];                 // in-degree histogram
__device__ int      g_start[MAX_N];               // CSR segment start (by dst)
__device__ int      g_cursor[MAX_N];              // scatter cursors
__device__ int      g_csr_src[MAX_EN];            // src node per CSR slot
__device__ float    g_ev[MAX_EN];                 // leaky-relu logit per CSR slot
__device__ int      g_total;                      // allocator cursor
__device__ int      g_is64;

// ---------------- kernels ----------------

// Zero histogram + allocator + detect int64 vs int32 edge_index.
__global__ void k_zero(const long long* ei, int n) {
    int i = blockIdx.x * blockDim.x + threadIdx.x;
    if (i < n) g_deg[i] = 0;
    if (i == 0) {
        g_total = 0;
        bool ok = true;
#pragma unroll
        for (int t = 0; t < 8; t++) {
            long long v = ei[t];
            if (v < 0 || v >= (long long)n) ok = false;
        }
        g_is64 = ok ? 1 : 0;
    }
}

// Histogram of destinations (incl. self loops appended at the end).
__global__ void k_hist(const void* ei, int E, int n) {
    int i = blockIdx.x * blockDim.x + threadIdx.x;
    if (i >= E + n) return;
    int d;
    if (i >= E) d = i - E;
    else if (g_is64) d = (int)((const long long*)ei)[i + E];
    else             d = ((const int*)ei)[i + E];
    atomicAdd(&g_deg[d], 1);
}

// ---------------- GEMM: bf16-split tensor-core, term-major mma ordering ------
// xw = x @ W. Block tile 64x128, BK=32, 256 threads = 8 warps (4 row x 2 col),
// warp tile 16x64 (4 acc frags of 16x16).
// fp32 -> hi bf16 + lo bf16 (split once per tile in smem).
// acc += a_lo*b_hi + a_hi*b_lo + a_hi*b_hi (term-major: dependent mmas on the
// same acc are 4 issues apart, not back-to-back like the R7 version).
#define LDA 40
#define LDB 136

__global__ __launch_bounds__(256, 2) void k_gemm(const float* __restrict__ x,
                                                 const float* __restrict__ W,
                                                 int n) {
    __shared__ __nv_bfloat16 Ah[64][LDA], Al[64][LDA];
    __shared__ __nv_bfloat16 Bh[32][LDB], Bl[32][LDB];
    const int tid = threadIdx.x;
    const int warp = tid >> 5;
    const int wm = (warp & 3) * 16;      // warp row offset (4 groups of 16)
    const int wn = (warp >> 2) * 64;     // warp col offset (2 groups of 64)
    const int row0 = blockIdx.x * 64;

    wmma::fragment<wmma::accumulator, 16, 16, 16, float> acc[4];
#pragma unroll
    for (int j = 0; j < 4; j++) wmma::fill_fragment(acc[j], 0.0f);

    for (int k0 = 0; k0 < DIN; k0 += 32) {
        // A tile 64x32: 512 float4, 2 per thread; split hi/lo
#pragma unroll
        for (int h = 0; h < 2; h++) {
            int f = tid + h * 256;
            int r = f >> 3, kq = (f & 7) * 4;
            int row = row0 + r; if (row >= n) row = n - 1;
            float4 v = *(const float4*)(x + (size_t)row * DIN + k0 + kq);
            float vv[4] = {v.x, v.y, v.z, v.w};
#pragma unroll
            for (int e = 0; e < 4; e++) {
                __nv_bfloat16 hi = __float2bfloat16(vv[e]);
                Ah[r][kq + e] = hi;
                Al[r][kq + e] = __float2bfloat16(vv[e] - __bfloat162float(hi));
            }
        }
        // B tile 32x128: 1024 float4, 4 per thread; split hi/lo
#pragma unroll
        for (int h = 0; h < 4; h++) {
            int f = tid + h * 256;
            int kr = f >> 5, c = (f & 31) * 4;
            float4 v = *(const float4*)(W + (size_t)(k0 + kr) * DOUT + c);
            float vv[4] = {v.x, v.y, v.z, v.w};
#pragma unroll
            for (int e = 0; e < 4; e++) {
                __nv_bfloat16 hi = __float2bfloat16(vv[e]);
                Bh[kr][c + e] = hi;
                Bl[kr][c + e] = __float2bfloat16(vv[e] - __bfloat162float(hi));
            }
        }
        __syncthreads();

#pragma unroll
        for (int ks = 0; ks < 32; ks += 16) {
            wmma::fragment<wmma::matrix_a, 16, 16, 16, __nv_bfloat16, wmma::row_major> a_hi, a_lo;
            wmma::load_matrix_sync(a_hi, &Ah[wm][ks], LDA);
            wmma::load_matrix_sync(a_lo, &Al[wm][ks], LDA);
            wmma::fragment<wmma::matrix_b, 16, 16, 16, __nv_bfloat16, wmma::row_major> b_hi[4], b_lo[4];
#pragma unroll
            for (int j = 0; j < 4; j++) {
                wmma::load_matrix_sync(b_hi[j], &Bh[ks][wn + j * 16], LDB);
                wmma::load_matrix_sync(b_lo[j], &Bl[ks][wn + j * 16], LDB);
            }
            // term-major: 4 independent mmas between dependent ones
#pragma unroll
            for (int j = 0; j < 4; j++) wmma::mma_sync(acc[j], a_lo, b_hi[j], acc[j]);
#pragma unroll
            for (int j = 0; j < 4; j++) wmma::mma_sync(acc[j], a_hi, b_lo[j], acc[j]);
#pragma unroll
            for (int j = 0; j < 4; j++) wmma::mma_sync(acc[j], a_hi, b_hi[j], acc[j]);
        }
        __syncthreads();
    }

    // store fp32 (rows beyond n land in MAX_N slack, never read)
#pragma unroll
    for (int j = 0; j < 4; j++)
        wmma::store_matrix_sync(g_xw + (size_t)(row0 + wm) * DOUT + wn + j * 16,
                                acc[j], DOUT, wmma::mem_row_major);
}

// Per-node attention logits (one warp per row) + fused fp16 conversion of xw.
__global__ void k_rowdot(const float* __restrict__ att_src,
                         const float* __restrict__ att_dst, int n) {
    int gtid = blockIdx.x * blockDim.x + threadIdx.x;
    int w = gtid >> 5, lane = gtid & 31;
    if (w >= n) return;
    float4 v = ((const float4*)(g_xw + (size_t)w * DOUT))[lane];
    float4 s = ((const float4*)att_src)[lane];
    float4 d = ((const float4*)att_dst)[lane];
    float ps = v.x * s.x + v.y * s.y + v.z * s.z + v.w * s.w;
    float pd = v.x * d.x + v.y * d.y + v.z * d.z + v.w * d.w;

    __half2 h0 = __floats2half2_rn(v.x, v.y);
    __half2 h1 = __floats2half2_rn(v.z, v.w);
    uint2 u; u.x = *(unsigned*)&h0; u.y = *(unsigned*)&h1;
    *(uint2*)(g_xw_h + (size_t)w * DOUT + lane * 4) = u;

#pragma unroll
    for (int o = 16; o; o >>= 1) {
        ps += __shfl_xor_sync(0xffffffffu, ps, o);
        pd += __shfl_xor_sync(0xffffffffu, pd, o);
    }
    if (lane == 0) { g_asrc[w] = ps; g_adst[w] = pd; }
}

// One-pass segment allocation: warp prefix-scan of degrees + one atomicAdd
// per warp. Segment order is arbitrary but contiguous/disjoint.
__global__ void k_alloc(int n) {
    int i = blockIdx.x * blockDim.x + threadIdx.x;
    int lane = threadIdx.x & 31;
    int d = (i < n) ? g_deg[i] : 0;
    int sc = d;
#pragma unroll
    for (int off = 1; off < 32; off <<= 1) {
        int t = __shfl_up_sync(0xffffffffu, sc, off);
        if (lane >= off) sc += t;
    }
    int base = 0;
    if (lane == 31) base = atomicAdd(&g_total, sc);
    base = __shfl_sync(0xffffffffu, base, 31);
    if (i < n) {
        int st = base + sc - d;
        g_start[i] = st;
        g_cursor[i] = st;
    }
}

// Scatter edges into CSR order + fused leaky-relu logit (no max pass:
// logits are bounded |e| <= ~26, exp() safe in fp32).
__global__ void k_scatter(const void* ei, int E, int n) {
    int i = blockIdx.x * blockDim.x + threadIdx.x;
    if (i >= E + n) return;
    int s, d;
    if (i >= E) { s = d = i - E; }
    else if (g_is64) {
        const long long* p = (const long long*)ei;
        s = (int)p[i]; d = (int)p[i + E];
    } else {
        const int* p = (const int*)ei;
        s = p[i]; d = p[i + E];
    }
    float e = g_asrc[s] + g_adst[d];
    e = (e > 0.0f) ? e : NEG_SLOPE * e;
    int pos = atomicAdd(&g_cursor[d], 1);
    g_csr_src[pos] = s;
    g_ev[pos] = e;
}

// Fused GAT gather: softmax (no max shift) + weighted aggregate + bias + ELU.
// One warp per dst node; unroll-4 batches with exact tail (measured-best).
__global__ __launch_bounds__(256) void k_gat(float* __restrict__ out,
                                             const float* __restrict__ bias,
                                             int n) {
    int gtid = blockIdx.x * blockDim.x + threadIdx.x;
    int w = gtid >> 5, lane = gtid & 31;
    if (w >= n) return;
    const int s0 = g_start[w];
    const int s1 = s0 + g_deg[w];

    float4 acc = make_float4(0.f, 0.f, 0.f, 0.f);
    float denom = 0.f;
    const __half* xh = g_xw_h;
    int j = s0;
    for (; j + 4 <= s1; j += 4) {
        int  i0 = g_csr_src[j],     i1 = g_csr_src[j + 1];
        int  i2 = g_csr_src[j + 2], i3 = g_csr_src[j + 3];
        float e0 = g_ev[j],     e1 = g_ev[j + 1];
        float e2 = g_ev[j + 2], e3 = g_ev[j + 3];
        uint2 u0 = __ldg(((const uint2*)(xh + (size_t)i0 * DOUT)) + lane);
        uint2 u1 = __ldg(((const uint2*)(xh + (size_t)i1 * DOUT)) + lane);
        uint2 u2 = __ldg(((const uint2*)(xh + (size_t)i2 * DOUT)) + lane);
        uint2 u3 = __ldg(((const uint2*)(xh + (size_t)i3 * DOUT)) + lane);
        float a0 = __expf(e0), a1 = __expf(e1);
        float a2 = __expf(e2), a3 = __expf(e3);
        denom += (a0 + a1) + (a2 + a3);
        float2 f;
        f = __half22float2(*(__half2*)&u0.x); acc.x += a0 * f.x; acc.y += a0 * f.y;
        f = __half22float2(*(__half2*)&u0.y); acc.z += a0 * f.x; acc.w += a0 * f.y;
        f = __half22float2(*(__half2*)&u1.x); acc.x += a1 * f.x; acc.y += a1 * f.y;
        f = __half22float2(*(__half2*)&u1.y); acc.z += a1 * f.x; acc.w += a1 * f.y;
        f = __half22float2(*(__half2*)&u2.x); acc.x += a2 * f.x; acc.y += a2 * f.y;
        f = __half22float2(*(__half2*)&u2.y); acc.z += a2 * f.x; acc.w += a2 * f.y;
        f = __half22float2(*(__half2*)&u3.x); acc.x += a3 * f.x; acc.y += a3 * f.y;
        f = __half22float2(*(__half2*)&u3.y); acc.z += a3 * f.x; acc.w += a3 * f.y;
    }
    for (; j < s1; j++) {
        int   i0 = g_csr_src[j];
        float a0 = __expf(g_ev[j]);
        uint2 u0 = __ldg(((const uint2*)(xh + (size_t)i0 * DOUT)) + lane);
        denom += a0;
        float2 f;
        f = __half22float2(*(__half2*)&u0.x); acc.x += a0 * f.x; acc.y += a0 * f.y;
        f = __half22float2(*(__half2*)&u0.y); acc.z += a0 * f.x; acc.w += a0 * f.y;
    }

    float r = 1.0f / denom;
    float4 b = ((const float4*)bias)[lane];
    float4 o;
    o.x = acc.x * r + b.x; o.y = acc.y * r + b.y;
    o.z = acc.z * r + b.z; o.w = acc.w * r + b.w;
    o.x = (o.x > 0.f) ? o.x : expm1f(o.x);
    o.y = (o.y > 0.f) ? o.y : expm1f(o.y);
    o.z = (o.z > 0.f) ? o.z : expm1f(o.z);
    o.w = (o.w > 0.f) ? o.w : expm1f(o.w);
    ((float4*)(out + (size_t)w * DOUT))[lane] = o;
}

// ---------------- launch ----------------
extern "C" void kernel_launch(void* const* d_in, const int* in_sizes, int n_in,
                              void* d_out, int out_size) {
    const float* x       = (const float*)d_in[0];
    const void*  ei      = d_in[1];
    const float* W       = (const float*)d_in[2];
    const float* att_src = (const float*)d_in[3];
    const float* att_dst = (const float*)d_in[4];
    const float* bias    = (const float*)d_in[5];
    float* out = (float*)d_out;

    const int n  = in_sizes[0] / DIN;
    const int E  = in_sizes[1] / 2;
    const int EN = E + n;

    k_zero<<<(n + 255) / 256, 256>>>((const long long*)ei, n);
    k_hist<<<(EN + 255) / 256, 256>>>(ei, E, n);
    k_gemm<<<(n + 63) / 64, 256>>>(x, W, n);
    k_rowdot<<<(n * 32 + 255) / 256, 256>>>(att_src, att_dst, n);
    k_alloc<<<(n + 255) / 256, 256>>>(n);
    k_scatter<<<(EN + 255) / 256, 256>>>(ei, E, n);
    k_gat<<<(n * 32 + 255) / 256, 256>>>(out, bias, n);
}